// round 1
// baseline (speedup 1.0000x reference)
#include <cuda_runtime.h>

// IFOPooling: h_t = f_t * h_{t-1} + i_t * z_t over the contiguous S axis.
// Inputs (metadata order): f [B,H,S], z [B,H,S], i [B,H,S], all fp32.
// Output: h [B,H,S] fp32. B=16, H=1024, S=2048 -> 16384 rows of 2048.
//
// One 256-thread block per row; 8 elements/thread; linear-recurrence scan
// via composition (a,b): h_out = a*h_in + b.

#define SEQ_LEN 2048
#define TPB 256
#define EPT 8            // elements per thread (TPB*EPT == SEQ_LEN)
#define NWARPS (TPB / 32)

__global__ __launch_bounds__(TPB) void ifo_scan_kernel(
    const float* __restrict__ f,
    const float* __restrict__ z,
    const float* __restrict__ in_i,
    float* __restrict__ out)
{
    const size_t base = (size_t)blockIdx.x * SEQ_LEN;
    const int t    = threadIdx.x;
    const int lane = t & 31;
    const int wid  = t >> 5;
    const size_t off = base + (size_t)t * EPT;

    // ---- vectorized loads (2x float4 per input) ----
    const float4 fA = *reinterpret_cast<const float4*>(f    + off);
    const float4 fB = *reinterpret_cast<const float4*>(f    + off + 4);
    const float4 zA = *reinterpret_cast<const float4*>(z    + off);
    const float4 zB = *reinterpret_cast<const float4*>(z    + off + 4);
    const float4 iA = *reinterpret_cast<const float4*>(in_i + off);
    const float4 iB = *reinterpret_cast<const float4*>(in_i + off + 4);

    float fv[EPT] = {fA.x, fA.y, fA.z, fA.w, fB.x, fB.y, fB.z, fB.w};
    float xv[EPT] = {iA.x * zA.x, iA.y * zA.y, iA.z * zA.z, iA.w * zA.w,
                     iB.x * zB.x, iB.y * zB.y, iB.z * zB.z, iB.w * zB.w};

    // ---- thread-local composition over 8 elements: h -> a*h + b ----
    float a = 1.0f, b = 0.0f;
#pragma unroll
    for (int k = 0; k < EPT; k++) {
        a = fv[k] * a;
        b = fmaf(fv[k], b, xv[k]);
    }

    // ---- warp-inclusive scan of (a,b) via shuffles ----
    const unsigned mask = 0xffffffffu;
    float ia = a, ib = b;
#pragma unroll
    for (int d = 1; d < 32; d <<= 1) {
        float pa = __shfl_up_sync(mask, ia, d);
        float pb = __shfl_up_sync(mask, ib, d);
        if (lane >= d) {
            ib = fmaf(ia, pb, ib);   // compose: prev then cur
            ia = ia * pa;
        }
    }
    // exclusive within warp
    float ea = __shfl_up_sync(mask, ia, 1);
    float eb = __shfl_up_sync(mask, ib, 1);
    if (lane == 0) { ea = 1.0f; eb = 0.0f; }

    // ---- cross-warp exclusive scan of warp aggregates ----
    __shared__ float wa[NWARPS];
    __shared__ float wb[NWARPS];
    if (lane == 31) { wa[wid] = ia; wb[wid] = ib; }
    __syncthreads();
    if (t == 0) {
        float pa = 1.0f, pb = 0.0f;
#pragma unroll
        for (int w = 0; w < NWARPS; w++) {
            float ca = wa[w], cb = wb[w];
            wa[w] = pa; wb[w] = pb;
            pb = fmaf(ca, pb, cb);
            pa = ca * pa;
        }
    }
    __syncthreads();

    // h at the start of this thread's segment (h_{-1} = 0 => warp-start h = wb[wid])
    float h = fmaf(ea, wb[wid], eb);

    // ---- replay local recurrence with true prefix ----
#pragma unroll
    for (int k = 0; k < EPT; k++) {
        h = fmaf(fv[k], h, xv[k]);
        xv[k] = h;
    }

    // ---- vectorized stores ----
    float4 o0 = make_float4(xv[0], xv[1], xv[2], xv[3]);
    float4 o1 = make_float4(xv[4], xv[5], xv[6], xv[7]);
    *reinterpret_cast<float4*>(out + off)     = o0;
    *reinterpret_cast<float4*>(out + off + 4) = o1;
}

extern "C" void kernel_launch(void* const* d_in, const int* in_sizes, int n_in,
                              void* d_out, int out_size)
{
    const float* f  = (const float*)d_in[0];
    const float* z  = (const float*)d_in[1];
    const float* ii = (const float*)d_in[2];
    float* out = (float*)d_out;

    const int rows = out_size / SEQ_LEN;   // B*H = 16384
    ifo_scan_kernel<<<rows, TPB>>>(f, z, ii, out);
}